// round 16
// baseline (speedup 1.0000x reference)
#include <cuda_runtime.h>
#include <cuda_bf16.h>
#include <mma.h>
#include <math.h>
#include <cstdint>

using namespace nvcuda;

// ---------------------------------------------------------------------------
// SpatialTransformer — round 15: M-tile templated GEMM. MT=64 (grid 320,
// 2 blocks/SM) for the six grid-160 GEMMs; MT=128 for large-grid GEMMs.
// Rest as round 14.
// ---------------------------------------------------------------------------

#define L_TOK   4096
#define C_DIM   320
#define HEADS   8
#define DH      40
#define DHP     48
#define CTX_DIM 768
#define LCTX    77
#define LCTXP   128
#define FFI     1280
#define NGROUPS 32
#define CH_PER_G 10

typedef __nv_bfloat16 bf16;

// fp32 scratch
__device__ float g_t [L_TOK * C_DIM];
__device__ float g_part[NGROUPS * 8 * 2];
// bf16 activations (zero-initialized; pad lanes never written)
__device__ bf16 b_xn[L_TOK * C_DIM];
__device__ bf16 b_hn[L_TOK * C_DIM];
__device__ bf16 b_a [L_TOK * C_DIM];
__device__ bf16 b_gg[L_TOK * FFI];
__device__ bf16 b_t [L_TOK * C_DIM];
__device__ bf16 b_qh[HEADS * L_TOK * DHP];
__device__ bf16 b_kh[HEADS * L_TOK * DHP];
__device__ bf16 b_vh[HEADS * L_TOK * DHP];
__device__ bf16 b_k2h[HEADS * LCTXP * DHP];
__device__ bf16 b_v2h[HEADS * LCTXP * DHP];
__device__ bf16 b_ctx[LCTX * CTX_DIM];
// bf16 weights
__device__ bf16 b_w_in[C_DIM * C_DIM];
__device__ bf16 b_wq1[C_DIM * C_DIM];
__device__ bf16 b_wkv1[C_DIM * 2 * C_DIM];
__device__ bf16 b_wqkv1[C_DIM * 3 * C_DIM];
__device__ bf16 b_wo1[C_DIM * C_DIM];
__device__ bf16 b_wq2[C_DIM * C_DIM];
__device__ bf16 b_wkv2[CTX_DIM * 2 * C_DIM];
__device__ bf16 b_wo2[C_DIM * C_DIM];
__device__ bf16 b_wff1[C_DIM * 2 * FFI];
__device__ bf16 b_wff2[FFI * C_DIM];
__device__ bf16 b_wout[C_DIM * C_DIM];

// ---------------- helpers ----------------
__device__ __forceinline__ unsigned int smem_u32(const void* p)
{ return (unsigned int)__cvta_generic_to_shared(p); }

__device__ __forceinline__ void cp16(unsigned int dst, const void* src, int sz)
{ asm volatile("cp.async.cg.shared.global [%0], [%1], 16, %2;\n"
               :: "r"(dst), "l"(src), "r"(sz)); }

__device__ __forceinline__ void cp_commit()
{ asm volatile("cp.async.commit_group;\n"); }

template<int N> __device__ __forceinline__ void cp_wait()
{ asm volatile("cp.async.wait_group %0;\n" :: "n"(N)); }

__device__ __forceinline__ float ex2(float x)
{ float r; asm("ex2.approx.f32 %0, %1;" : "=f"(r) : "f"(x)); return r; }

__device__ __forceinline__ void mma16816(float* c,
    unsigned a0, unsigned a1, unsigned a2, unsigned a3,
    unsigned b0, unsigned b1)
{
    asm volatile(
        "mma.sync.aligned.m16n8k16.row.col.f32.bf16.bf16.f32 "
        "{%0,%1,%2,%3}, {%4,%5,%6,%7}, {%8,%9}, {%0,%1,%2,%3};"
        : "+f"(c[0]), "+f"(c[1]), "+f"(c[2]), "+f"(c[3])
        : "r"(a0), "r"(a1), "r"(a2), "r"(a3), "r"(b0), "r"(b1));
}

__device__ __forceinline__ void mma16808(float* c,
    unsigned a0, unsigned a1, unsigned b0)
{
    asm volatile(
        "mma.sync.aligned.m16n8k8.row.col.f32.bf16.bf16.f32 "
        "{%0,%1,%2,%3}, {%4,%5}, {%6}, {%0,%1,%2,%3};"
        : "+f"(c[0]), "+f"(c[1]), "+f"(c[2]), "+f"(c[3])
        : "r"(a0), "r"(a1), "r"(b0));
}

// ---------------- fused prep ----------------
struct CvtJobs {
    const float4* s[9];
    __nv_bfloat162* d[9];
    int n[9];
};

__global__ __launch_bounds__(256) void prep_kernel(
    CvtJobs J,
    const float4* wk1, const float4* wv1, __nv_bfloat162* dkv1,
    const float4* wk2, const float4* wv2, __nv_bfloat162* dkv2,
    const float4* wq1f, __nv_bfloat162* dqkv1,
    const float* __restrict__ x)
{
    int i0 = blockIdx.x * blockDim.x + threadIdx.x;
    int st = gridDim.x * blockDim.x;
    #pragma unroll
    for (int q = 0; q < 9; q++) {
        const float4* s = J.s[q];
        __nv_bfloat162* d = J.d[q];
        int n = J.n[q];
        for (int j = i0; j < n; j += st) {
            float4 v = s[j];
            d[2*j]   = __floats2bfloat162_rn(v.x, v.y);
            d[2*j+1] = __floats2bfloat162_rn(v.z, v.w);
        }
    }
    const int C4 = C_DIM / 4;
    {
        int n4 = C_DIM * C4;
        for (int j = i0; j < n4; j += st) {
            int k = j / C4, c4 = j % C4;
            float4 a = wk1[j];
            float4 b = wv1[j];
            __nv_bfloat162* row = dkv1 + k * C_DIM;
            row[c4*2]   = __floats2bfloat162_rn(a.x, a.y);
            row[c4*2+1] = __floats2bfloat162_rn(a.z, a.w);
            row[C_DIM/2 + c4*2]   = __floats2bfloat162_rn(b.x, b.y);
            row[C_DIM/2 + c4*2+1] = __floats2bfloat162_rn(b.z, b.w);
        }
    }
    {
        int n4 = C_DIM * C4;
        for (int j = i0; j < n4; j += st) {
            int k = j / C4, c4 = j % C4;
            float4 a = wq1f[j];
            __nv_bfloat162* row = dqkv1 + k * (3 * C_DIM / 2);
            row[c4*2]   = __floats2bfloat162_rn(a.x, a.y);
            row[c4*2+1] = __floats2bfloat162_rn(a.z, a.w);
        }
    }
    {
        int n4 = CTX_DIM * C4;
        for (int j = i0; j < n4; j += st) {
            int k = j / C4, c4 = j % C4;
            float4 a = wk2[j];
            float4 b = wv2[j];
            __nv_bfloat162* row = dkv2 + k * C_DIM;
            row[c4*2]   = __floats2bfloat162_rn(a.x, a.y);
            row[c4*2+1] = __floats2bfloat162_rn(a.z, a.w);
            row[C_DIM/2 + c4*2]   = __floats2bfloat162_rn(b.x, b.y);
            row[C_DIM/2 + c4*2+1] = __floats2bfloat162_rn(b.z, b.w);
        }
    }
    if (blockIdx.x < 256) {
        int b = blockIdx.x;
        int g = b >> 3, seg = b & 7;
        int tid = threadIdx.x;
        const int SEG4 = CH_PER_G * L_TOK / 4 / 8;
        const float4* base = (const float4*)(x + (size_t)g * CH_PER_G * L_TOK)
                             + seg * SEG4;
        float s = 0.f, ss = 0.f;
        for (int i = tid; i < SEG4; i += 256) {
            float4 v = base[i];
            s  += v.x + v.y + v.z + v.w;
            ss += v.x*v.x + v.y*v.y + v.z*v.z + v.w*v.w;
        }
        __shared__ float rs[256], rss[256];
        rs[tid] = s; rss[tid] = ss;
        __syncthreads();
        for (int o = 128; o > 0; o >>= 1) {
            if (tid < o) { rs[tid] += rs[tid + o]; rss[tid] += rss[tid + o]; }
            __syncthreads();
        }
        if (tid == 0) {
            g_part[b * 2]     = rs[0];
            g_part[b * 2 + 1] = rss[0];
        }
    }
}

// ---------------- GroupNorm apply ----------------
__global__ void gn_apply_kernel(const float* __restrict__ x,
                                const float* __restrict__ gw,
                                const float* __restrict__ gb,
                                bf16* __restrict__ out)
{
    __shared__ float tile[32][65];
    __shared__ float smean[NGROUPS], srstd[NGROUPS];
    if (threadIdx.x < NGROUPS) {
        int g = threadIdx.x;
        float s = 0.f, ss = 0.f;
        #pragma unroll
        for (int k = 0; k < 8; k++) {
            s  += g_part[(g * 8 + k) * 2];
            ss += g_part[(g * 8 + k) * 2 + 1];
        }
        const float NEL = (float)(CH_PER_G * L_TOK);
        float m = s / NEL;
        float var = ss / NEL - m * m;
        smean[g] = m;
        srstd[g] = rsqrtf(var + 1e-6f);
    }
    __syncthreads();

    int hw0 = blockIdx.x * 64;
    int c0  = blockIdx.y * 32;
    #pragma unroll
    for (int p = 0; p < 8; p++) {
        int i = threadIdx.x + p * 256;
        int c = i >> 6, hw = i & 63;
        int gc = c0 + c;
        int g = gc / CH_PER_G;
        float v = (x[(size_t)gc * L_TOK + hw0 + hw] - smean[g]) * srstd[g]
                  * gw[gc] + gb[gc];
        tile[c][hw] = v;
    }
    __syncthreads();
    #pragma unroll
    for (int p = 0; p < 8; p++) {
        int i = threadIdx.x + p * 256;
        int hw = i >> 5, c = i & 31;
        out[(size_t)(hw0 + hw) * C_DIM + c0 + c] = __float2bfloat16(tile[c][hw]);
    }
}

// ---------------- LayerNorm ----------------
__global__ __launch_bounds__(256) void ln_kernel(
    const float* __restrict__ in, const float* __restrict__ w,
    const float* __restrict__ b, bf16* __restrict__ out)
{
    int token = blockIdx.x * 8 + (threadIdx.x >> 5);
    int lane = threadIdx.x & 31;
    const float4* row4 = (const float4*)(in + (size_t)token * C_DIM);
    float s = 0.f, ss = 0.f;
    float4 va[3];
    #pragma unroll
    for (int j = 0; j < 3; j++) {
        int idx = lane + j * 32;
        if (idx < 80) {
            float4 v = row4[idx];
            va[j] = v;
            s  += v.x + v.y + v.z + v.w;
            ss += v.x*v.x + v.y*v.y + v.z*v.z + v.w*v.w;
        }
    }
    #pragma unroll
    for (int o = 16; o > 0; o >>= 1) {
        s  += __shfl_xor_sync(0xffffffffu, s, o);
        ss += __shfl_xor_sync(0xffffffffu, ss, o);
    }
    float m = s / (float)C_DIM;
    float var = ss / (float)C_DIM - m * m;
    float r = rsqrtf(var + 1e-5f);

    const float4* w4 = (const float4*)w;
    const float4* b4 = (const float4*)b;
    __nv_bfloat162* o2 = (__nv_bfloat162*)(out + (size_t)token * C_DIM);
    #pragma unroll
    for (int j = 0; j < 3; j++) {
        int idx = lane + j * 32;
        if (idx < 80) {
            float4 v = va[j];
            float4 ww = w4[idx];
            float4 bb = b4[idx];
            o2[idx * 2]     = __floats2bfloat162_rn((v.x - m) * r * ww.x + bb.x,
                                                    (v.y - m) * r * ww.y + bb.y);
            o2[idx * 2 + 1] = __floats2bfloat162_rn((v.z - m) * r * ww.z + bb.z,
                                                    (v.w - m) * r * ww.w + bb.w);
        }
    }
}

// ---------------- bf16 TC GEMM, MT x 64, 256 thr, 3-stage ----------------
template<int MT, bool DUAL> struct GemmBufT {
    bf16 As[3][MT][40];
    bf16 Bs[3][DUAL ? 2 : 1][32][72];
};
#define GEMM_SMEM(MT, DUAL) ((int)sizeof(GemmBufT<MT, DUAL>))

template<int MT, bool DUAL>
__global__ __launch_bounds__(256) void gemm_bf16_kernel(
    const bf16* __restrict__ A, const bf16* __restrict__ B,
    const float* __restrict__ bias, const float* __restrict__ res,
    float* __restrict__ Cf, bf16* __restrict__ Cbf, int ldcBf,
    bf16* __restrict__ dst0, bf16* __restrict__ dst1, bf16* __restrict__ dst2,
    float scale0, int Lpad,
    bf16* __restrict__ ggOut,
    int M, int N, int K, int transOut)
{
    constexpr int AF = MT / 64;       // 16-row A-fragments per warp
    extern __shared__ char smraw[];
    GemmBufT<MT, DUAL>* in = (GemmBufT<MT, DUAL>*)smraw;
    float (*Cs)[68] = (float(*)[68])smraw;

    int bm = blockIdx.y * MT;
    int bn = blockIdx.x * 64;
    int tid = threadIdx.x;
    int w = tid >> 5, wm = w >> 1, wn = w & 1;
    int rb = wm * 16 * AF;            // warp row base

    wmma::fragment<wmma::accumulator, 16, 16, 16, float> acc[AF][2];
    wmma::fragment<wmma::accumulator, 16, 16, 16, float> acc2[DUAL ? AF : 1][2];
    #pragma unroll
    for (int i = 0; i < AF; i++)
        #pragma unroll
        for (int j = 0; j < 2; j++) wmma::fill_fragment(acc[i][j], 0.f);
    if (DUAL) {
        #pragma unroll
        for (int i = 0; i < AF; i++)
            #pragma unroll
            for (int j = 0; j < 2; j++) wmma::fill_fragment(acc2[i][j], 0.f);
    }

    auto issue = [&](int s, int k0) {
        #pragma unroll
        for (int p = 0; p < MT / 64; p++) {
            int c = tid + p * 256;
            int row = c >> 2, ch = c & 3;
            int gm = bm + row;
            const bf16* src = A + (size_t)(gm < M ? gm : 0) * K + k0 + ch * 8;
            cp16(smem_u32(&in->As[s][row][ch * 8]), src, (gm < M) ? 16 : 0);
        }
        {
            int row = tid >> 3, ch = tid & 7;
            const bf16* src = B + (size_t)(k0 + row) * N + bn + ch * 8;
            cp16(smem_u32(&in->Bs[s][0][row][ch * 8]), src, 16);
            if (DUAL)
                cp16(smem_u32(&in->Bs[s][DUAL ? 1 : 0][row][ch * 8]), src + FFI, 16);
        }
        cp_commit();
    };

    int nk = K / 32;
    issue(0, 0);
    issue(1, 32);
    for (int ki = 0; ki < nk; ki++) {
        int s = ki - (ki / 3) * 3;
        if (ki == nk - 1) cp_wait<0>(); else cp_wait<1>();
        __syncthreads();
        #pragma unroll
        for (int ks = 0; ks < 2; ks++) {
            wmma::fragment<wmma::matrix_a, 16, 16, 16, bf16, wmma::row_major> af[AF];
            wmma::fragment<wmma::matrix_b, 16, 16, 16, bf16, wmma::row_major> bfr[2];
            #pragma unroll
            for (int i = 0; i < AF; i++)
                wmma::load_matrix_sync(af[i], &in->As[s][rb + i * 16][ks * 16], 40);
            wmma::load_matrix_sync(bfr[0], &in->Bs[s][0][ks*16][wn*32     ], 72);
            wmma::load_matrix_sync(bfr[1], &in->Bs[s][0][ks*16][wn*32 + 16], 72);
            #pragma unroll
            for (int i = 0; i < AF; i++)
                #pragma unroll
                for (int j = 0; j < 2; j++)
                    wmma::mma_sync(acc[i][j], af[i], bfr[j], acc[i][j]);
            if (DUAL) {
                wmma::load_matrix_sync(bfr[0], &in->Bs[s][DUAL?1:0][ks*16][wn*32     ], 72);
                wmma::load_matrix_sync(bfr[1], &in->Bs[s][DUAL?1:0][ks*16][wn*32 + 16], 72);
                #pragma unroll
                for (int i = 0; i < AF; i++)
                    #pragma unroll
                    for (int j = 0; j < 2; j++)
                        wmma::mma_sync(acc2[i][j], af[i], bfr[j], acc2[i][j]);
            }
        }
        if (ki + 2 < nk) {
            int s2 = (ki + 2) - ((ki + 2) / 3) * 3;
            issue(s2, (ki + 2) * 32);
        }
    }
    __syncthreads();

    // ---- epilogue ----
    #pragma unroll
    for (int i = 0; i < AF; i++)
        #pragma unroll
        for (int j = 0; j < 2; j++)
            wmma::store_matrix_sync(&Cs[rb + i*16][wn*32 + j*16],
                                    acc[i][j], 68, wmma::mem_row_major);
    __syncthreads();

    constexpr int EP = MT / 4;    // per-thread epilogue elems

    if (DUAL) {
        float rA[EP];
        #pragma unroll
        for (int p = 0; p < EP; p++) {
            int i = tid + p * 256;
            rA[p] = Cs[i >> 6][i & 63];
        }
        __syncthreads();
        #pragma unroll
        for (int i = 0; i < AF; i++)
            #pragma unroll
            for (int j = 0; j < 2; j++)
                wmma::store_matrix_sync(&Cs[rb + i*16][wn*32 + j*16],
                                        acc2[i][j], 68, wmma::mem_row_major);
        __syncthreads();
        #pragma unroll
        for (int p = 0; p < EP; p++) {
            int i = tid + p * 256;
            int m = i >> 6, n = i & 63;
            int gm = bm + m, gn = bn + n;
            float av = rA[p] + bias[gn];
            float gv = Cs[m][n] + bias[gn + FFI];
            float ge = 0.5f * gv * (1.f + erff(gv * 0.70710678118654752f));
            ggOut[(size_t)gm * FFI + gn] = __float2bfloat16(av * ge);
        }
        return;
    }

    if (transOut) {
        #pragma unroll
        for (int p = 0; p < EP; p++) {
            int i = tid + p * 256;
            int m = i % MT, n = i / MT;
            int gm = bm + m, gn = bn + n;
            float v = Cs[m][n];
            if (bias) v += bias[gn];
            size_t idx = (size_t)gn * M + gm;
            if (res) v += res[idx];
            Cf[idx] = v;
        }
        return;
    }

    #pragma unroll
    for (int p = 0; p < EP; p++) {
        int i = tid + p * 256;
        int m = i >> 6, n = i & 63;
        int gm = bm + m, gn = bn + n;
        if (gm >= M) continue;
        float v = Cs[m][n];
        if (bias) v += bias[gn];
        if (Cf) {
            size_t idx = (size_t)gm * N + gn;
            if (res) v += res[idx];
            Cf[idx] = v;
        }
        if (Cbf) Cbf[(size_t)gm * ldcBf + gn] = __float2bfloat16(v);
        if (dst0) {
            int which = gn / C_DIM;
            int cc = gn - which * C_DIM;
            bf16* d = (which == 0) ? dst0 : ((which == 1) ? dst1 : dst2);
            float sc = (which == 0) ? scale0 : 1.f;
            int h = cc & 7, j = cc >> 3;
            d[((size_t)h * Lpad + gm) * DHP + j] = __float2bfloat16(v * sc);
        }
    }
}

// ---------------- FA2 attention, exact dh=40 ----------------
#define ATTN_SMEM (3 * 3072 * 2 * 2 + 128 * 48 * 2)   // 49152

__global__ __launch_bounds__(256, 2) void attn_reg_kernel(
    const bf16* __restrict__ qh, const bf16* __restrict__ kh,
    const bf16* __restrict__ vh, bf16* __restrict__ Obf,
    int Lk, int Lpad)
{
    extern __shared__ char smraw[];
    bf16* sK = (bf16*)smraw;
    bf16* sV = sK + 3 * 3072;
    bf16* sQ = sV + 3 * 3072;

    int h = blockIdx.y;
    int qbase = blockIdx.x * 128;
    int tid = threadIdx.x, w = tid >> 5, lane = tid & 31;
    int r0 = lane >> 2, cq = (lane & 3) * 2;

    auto load_kv = [&](int s, int k0) {
        const bf16* kp = kh + ((size_t)h * Lpad + k0) * DHP;
        const bf16* vp = vh + ((size_t)h * Lpad + k0) * DHP;
        #pragma unroll
        for (int p = 0; p < 3; p++) {
            int c = tid + p * 256;
            if (c < 384) cp16(smem_u32(&sK[s * 3072 + c * 8]), kp + c * 8, 16);
            else         cp16(smem_u32(&sV[s * 3072 + (c - 384) * 8]),
                              vp + (c - 384) * 8, 16);
        }
        cp_commit();
    };

    int ntiles = (Lk + 63) / 64;
    load_kv(0, 0);
    if (ntiles > 1) load_kv(1, 64);

    {
        const uint4* src = (const uint4*)(qh + ((size_t)h * L_TOK + qbase) * DHP);
        uint4* dst = (uint4*)sQ;
        #pragma unroll
        for (int p = 0; p < 3; p++) dst[tid + p * 256] = src[tid + p * 256];
    }
    __syncthreads();

    unsigned qa[2][4], qa8[2];
    {
        const bf16* qrow = sQ + (w * 16 + r0) * 48;
        #pragma unroll
        for (int kd = 0; kd < 2; kd++) {
            qa[kd][0] = *(const unsigned*)(qrow + kd * 16 + cq);
            qa[kd][1] = *(const unsigned*)(qrow + 8 * 48 + kd * 16 + cq);
            qa[kd][2] = *(const unsigned*)(qrow + kd * 16 + 8 + cq);
            qa[kd][3] = *(const unsigned*)(qrow + 8 * 48 + kd * 16 + 8 + cq);
        }
        qa8[0] = *(const unsigned*)(qrow + 32 + cq);
        qa8[1] = *(const unsigned*)(qrow + 8 * 48 + 32 + cq);
    }

    float O[5][4] = {};
    float m0 = -1e30f, m1 = -1e30f, l0 = 0.f, l1 = 0.f;

    for (int ti = 0; ti < ntiles; ti++) {
        int s = ti - (ti / 3) * 3;
        int k0 = ti * 64;
        if (ti == ntiles - 1) cp_wait<0>(); else cp_wait<1>();
        __syncthreads();

        float S[8][4];
        #pragma unroll
        for (int j = 0; j < 8; j++)
            S[j][0] = S[j][1] = S[j][2] = S[j][3] = 0.f;
        #pragma unroll
        for (int j = 0; j < 8; j++) {
            const bf16* kb = &sK[s * 3072 + (j * 8 + r0) * 48];
            #pragma unroll
            for (int kd = 0; kd < 2; kd++) {
                unsigned b0 = *(const unsigned*)(kb + kd * 16 + cq);
                unsigned b1 = *(const unsigned*)(kb + kd * 16 + 8 + cq);
                mma16816(S[j], qa[kd][0], qa[kd][1], qa[kd][2], qa[kd][3], b0, b1);
            }
            unsigned b8 = *(const unsigned*)(kb + 32 + cq);
            mma16808(S[j], qa8[0], qa8[1], b8);
        }

        if (k0 + 64 > Lk) {
            #pragma unroll
            for (int j = 0; j < 8; j++) {
                int col = k0 + j * 8 + cq;
                if (col >= Lk)     { S[j][0] = -1e30f; S[j][2] = -1e30f; }
                if (col + 1 >= Lk) { S[j][1] = -1e30f; S[j][3] = -1e30f; }
            }
        }

        float mx0 = -1e30f, mx1 = -1e30f;
        #pragma unroll
        for (int j = 0; j < 8; j++) {
            mx0 = fmaxf(mx0, fmaxf(S[j][0], S[j][1]));
            mx1 = fmaxf(mx1, fmaxf(S[j][2], S[j][3]));
        }
        mx0 = fmaxf(mx0, __shfl_xor_sync(0xffffffffu, mx0, 1));
        mx0 = fmaxf(mx0, __shfl_xor_sync(0xffffffffu, mx0, 2));
        mx1 = fmaxf(mx1, __shfl_xor_sync(0xffffffffu, mx1, 1));
        mx1 = fmaxf(mx1, __shfl_xor_sync(0xffffffffu, mx1, 2));

        float mn0 = fmaxf(m0, mx0), mn1 = fmaxf(m1, mx1);
        float corr0 = ex2(m0 - mn0), corr1 = ex2(m1 - mn1);
        m0 = mn0; m1 = mn1;

        unsigned P[8][2];
        float sum0 = 0.f, sum1 = 0.f;
        #pragma unroll
        for (int j = 0; j < 8; j++) {
            float p0 = ex2(S[j][0] - mn0), p1 = ex2(S[j][1] - mn0);
            float p2 = ex2(S[j][2] - mn1), p3 = ex2(S[j][3] - mn1);
            sum0 += p0 + p1; sum1 += p2 + p3;
            __nv_bfloat162 u0 = __floats2bfloat162_rn(p0, p1);
            __nv_bfloat162 u1 = __floats2bfloat162_rn(p2, p3);
            P[j][0] = *(unsigned*)&u0;
            P[j][1] = *(unsigned*)&u1;
        }
        sum0 += __shfl_xor_sync(0xffffffffu, sum0, 1);
        sum0 += __shfl_xor_sync(0xffffffffu, sum0, 2);
        sum1 += __shfl_xor_sync(0xffffffffu, sum1, 1);
        sum1 += __shfl_xor_sync(0xffffffffu, sum1, 2);
        l0 = l0 * corr0 + sum0;
        l1 = l1 * corr1 + sum1;

        #pragma unroll
        for (int jd = 0; jd < 5; jd++) {
            O[jd][0] *= corr0; O[jd][1] *= corr0;
            O[jd][2] *= corr1; O[jd][3] *= corr1;
        }

        #pragma unroll
        for (int t = 0; t < 4; t++) {
            int g = lane >> 3;
            #pragma unroll
            for (int p2 = 0; p2 < 2; p2++) {
                unsigned addr = smem_u32(
                    &sV[s * 3072 + (t * 16 + (g & 1) * 8 + (lane & 7)) * 48
                        + p2 * 16 + (g >> 1) * 8]);
                unsigned v0, v1, v2, v3;
                asm volatile(
                    "ldmatrix.sync.aligned.m8n8.x4.trans.shared.b16 "
                    "{%0,%1,%2,%3}, [%4];"
                    : "=r"(v0), "=r"(v1), "=r"(v2), "=r"(v3) : "r"(addr));
                mma16816(O[2*p2],   P[2*t][0], P[2*t][1],
                                    P[2*t+1][0], P[2*t+1][1], v0, v1);
                mma16816(O[2*p2+1], P[2*t][0], P[2*t][1],
                                    P[2*t+1][0], P[2*t+1][1], v2, v3);
            }
            {
                unsigned addr = smem_u32(
                    &sV[s * 3072 + (t * 16 + ((lane >> 3) & 1) * 8 + (lane & 7)) * 48
                        + 32]);
                unsigned v0, v1;
                asm volatile(
                    "ldmatrix.sync.aligned.m8n8.x2.trans.shared.b16 "
                    "{%0,%1}, [%2];"
                    : "=r"(v0), "=r"(v1) : "r"(addr));
                mma16816(O[4], P[2*t][0], P[2*t][1],
                               P[2*t+1][0], P[2*t+1][1], v0, v1);
            }
        }

        if (ti + 2 < ntiles) {
            int s2 = (ti + 2) - ((ti + 2) / 3) * 3;
            load_kv(s2, (ti + 2) * 64);
        }
    }

    float il0 = 1.f / l0, il1 = 1.f / l1;
    int tok = qbase + w * 16 + r0;
    #pragma unroll
    for (int jd = 0; jd < 5; jd++) {
        int col = jd * 8 + cq;
        __nv_bfloat162 o0 = __floats2bfloat162_rn(O[jd][0] * il0, O[jd][1] * il0);
        __nv_bfloat162 o1 = __floats2bfloat162_rn(O[jd][2] * il1, O[jd][3] * il1);
        *(__nv_bfloat162*)(Obf + (size_t)tok * C_DIM + h * DH + col) = o0;
        *(__nv_bfloat162*)(Obf + (size_t)(tok + 8) * C_DIM + h * DH + col) = o1;
    }
}

// ---------------------------------------------------------------------------
extern "C" void kernel_launch(void* const* d_in, const int* in_sizes, int n_in,
                              void* d_out, int out_size)
{
    const float* x       = (const float*)d_in[0];
    const float* context = (const float*)d_in[1];
    const float* gn_w    = (const float*)d_in[2];
    const float* gn_b    = (const float*)d_in[3];
    const float* w_in    = (const float*)d_in[4];
    const float* b_in    = (const float*)d_in[5];
    const float* ln1_w   = (const float*)d_in[6];
    const float* ln1_b   = (const float*)d_in[7];
    const float* wq1     = (const float*)d_in[8];
    const float* wk1     = (const float*)d_in[9];
    const float* wv1     = (const float*)d_in[10];
    const float* wo1     = (const float*)d_in[11];
    const float* bo1     = (const float*)d_in[12];
    const float* ln2_w   = (const float*)d_in[13];
    const float* ln2_b   = (const float*)d_in[14];
    const float* wq2     = (const float*)d_in[15];
    const float* wk2     = (const float*)d_in[16];
    const float* wv2     = (const float*)d_in[17];
    const float* wo2     = (const float*)d_in[18];
    const float* bo2     = (const float*)d_in[19];
    const float* ln3_w   = (const float*)d_in[20];
    const float* ln3_b   = (const float*)d_in[21];
    const float* wff1    = (const float*)d_in[22];
    const float* bff1    = (const float*)d_in[23];
    const float* wff2    = (const float*)d_in[24];
    const float* bff2    = (const float*)d_in[25];
    const float* w_out   = (const float*)d_in[26];
    const float* b_out   = (const float*)d_in[27];
    float* out = (float*)d_out;

    static float *t = nullptr;
    static bf16 *xn, *hn, *a, *gg, *tb, *qh, *kh, *vh, *k2h, *v2h, *ctx;
    static bf16 *cw_in, *cwq1, *cwkv1, *cwqkv1, *cwo1, *cwq2, *cwkv2, *cwo2,
                *cwff1, *cwff2, *cwout;
    static bool init_done = false;
    if (!init_done) {
        cudaGetSymbolAddress((void**)&t,  g_t);
        cudaGetSymbolAddress((void**)&xn, b_xn);
        cudaGetSymbolAddress((void**)&hn, b_hn);
        cudaGetSymbolAddress((void**)&a,  b_a);
        cudaGetSymbolAddress((void**)&gg, b_gg);
        cudaGetSymbolAddress((void**)&tb, b_t);
        cudaGetSymbolAddress((void**)&qh, b_qh);
        cudaGetSymbolAddress((void**)&kh, b_kh);
        cudaGetSymbolAddress((void**)&vh, b_vh);
        cudaGetSymbolAddress((void**)&k2h, b_k2h);
        cudaGetSymbolAddress((void**)&v2h, b_v2h);
        cudaGetSymbolAddress((void**)&ctx, b_ctx);
        cudaGetSymbolAddress((void**)&cw_in, b_w_in);
        cudaGetSymbolAddress((void**)&cwq1, b_wq1);
        cudaGetSymbolAddress((void**)&cwkv1, b_wkv1);
        cudaGetSymbolAddress((void**)&cwqkv1, b_wqkv1);
        cudaGetSymbolAddress((void**)&cwo1, b_wo1);
        cudaGetSymbolAddress((void**)&cwq2, b_wq2);
        cudaGetSymbolAddress((void**)&cwkv2, b_wkv2);
        cudaGetSymbolAddress((void**)&cwo2, b_wo2);
        cudaGetSymbolAddress((void**)&cwff1, b_wff1);
        cudaGetSymbolAddress((void**)&cwff2, b_wff2);
        cudaGetSymbolAddress((void**)&cwout, b_wout);
        cudaFuncSetAttribute(gemm_bf16_kernel<128, false>,
                             cudaFuncAttributeMaxDynamicSharedMemorySize,
                             GEMM_SMEM(128, false));
        cudaFuncSetAttribute(gemm_bf16_kernel<128, true>,
                             cudaFuncAttributeMaxDynamicSharedMemorySize,
                             GEMM_SMEM(128, true));
        cudaFuncSetAttribute(gemm_bf16_kernel<64, false>,
                             cudaFuncAttributeMaxDynamicSharedMemorySize,
                             GEMM_SMEM(64, false));
        cudaFuncSetAttribute(attn_reg_kernel,
                             cudaFuncAttributeMaxDynamicSharedMemorySize,
                             ATTN_SMEM);
        init_done = true;
    }

    const float scaleQ = 0.15811388300841898f * 1.4426950408889634f;
    const int CC4 = C_DIM * C_DIM / 4;

    CvtJobs J;
    J.s[0] = (const float4*)context; J.d[0] = (__nv_bfloat162*)ctx;   J.n[0] = LCTX * CTX_DIM / 4;
    J.s[1] = (const float4*)w_in;    J.d[1] = (__nv_bfloat162*)cw_in; J.n[1] = CC4;
    J.s[2] = (const float4*)wq1;     J.d[2] = (__nv_bfloat162*)cwq1;  J.n[2] = CC4;
    J.s[3] = (const float4*)wo1;     J.d[3] = (__nv_bfloat162*)cwo1;  J.n[3] = CC4;
    J.s[4] = (const float4*)wq2;     J.d[4] = (__nv_bfloat162*)cwq2;  J.n[4] = CC4;
    J.s[5] = (const float4*)wo2;     J.d[5] = (__nv_bfloat162*)cwo2;  J.n[5] = CC4;
    J.s[6] = (const float4*)wff1;    J.d[6] = (__nv_bfloat162*)cwff1; J.n[6] = C_DIM * 2 * FFI / 4;
    J.s[7] = (const float4*)wff2;    J.d[7] = (__nv_bfloat162*)cwff2; J.n[7] = FFI * C_DIM / 4;
    J.s[8] = (const float4*)w_out;   J.d[8] = (__nv_bfloat162*)cwout; J.n[8] = CC4;
    prep_kernel<<<512, 256>>>(J,
        (const float4*)wk1, (const float4*)wv1, (__nv_bfloat162*)cwkv1,
        (const float4*)wk2, (const float4*)wv2, (__nv_bfloat162*)cwkv2,
        (const float4*)wq1, (__nv_bfloat162*)cwqkv1,
        x);

    // compose wqkv1 cols [320,960) = wq1 @ [wk1 | wv1]
    {
        dim3 gComp(2 * C_DIM / 64, (C_DIM + 127) / 128);   // (10, 3)
        gemm_bf16_kernel<128, false><<<gComp, 256, GEMM_SMEM(128, false)>>>(
            cwq1, cwkv1, nullptr, nullptr, nullptr,
            cwqkv1 + C_DIM, 3 * C_DIM,
            nullptr, nullptr, nullptr, 0.f, 0, nullptr,
            C_DIM, 2 * C_DIM, C_DIM, 0);
    }

    dim3 g320s(C_DIM / 64, L_TOK / 64);       // (5, 64) MT=64 -> 320 blocks
    dim3 gQKV(3 * C_DIM / 64, L_TOK / 128);   // (15, 32) MT=128
    dim3 gKVc(2 * C_DIM / 64, 1);             // MT=128
    dim3 gFF1(FFI / 64, L_TOK / 128);         // (20, 32) MT=128 dual
    dim3 attnGrid(L_TOK / 128, HEADS);

    gn_apply_kernel<<<dim3(L_TOK / 64, C_DIM / 32), 256>>>(x, gn_w, gn_b, xn);
    gemm_bf16_kernel<64, false><<<g320s, 256, GEMM_SMEM(64, false)>>>(
        xn, cw_in, b_in, nullptr, t, nullptr, 0,
        nullptr, nullptr, nullptr, 0.f, 0, nullptr,
        L_TOK, C_DIM, C_DIM, 0);

    // ---- self-attention: LN -> fused QKV GEMM -> attn -> out-proj ----
    ln_kernel<<<L_TOK / 8, 256>>>(t, ln1_w, ln1_b, hn);
    gemm_bf16_kernel<128, false><<<gQKV, 256, GEMM_SMEM(128, false)>>>(
        hn, cwqkv1, nullptr, nullptr, nullptr, nullptr, 0,
        qh, kh, vh, scaleQ, L_TOK, nullptr,
        L_TOK, 3 * C_DIM, C_DIM, 0);
    attn_reg_kernel<<<attnGrid, 256, ATTN_SMEM>>>(qh, kh, vh, a, L_TOK, L_TOK);
    gemm_bf16_kernel<64, false><<<g320s, 256, GEMM_SMEM(64, false)>>>(
        a, cwo1, bo1, t, t, nullptr, 0,
        nullptr, nullptr, nullptr, 0.f, 0, nullptr,
        L_TOK, C_DIM, C_DIM, 0);

    // ---- cross-attention ----
    ln_kernel<<<L_TOK / 8, 256>>>(t, ln2_w, ln2_b, hn);
    gemm_bf16_kernel<64, false><<<g320s, 256, GEMM_SMEM(64, false)>>>(
        hn, cwq2, nullptr, nullptr, nullptr, nullptr, 0,
        qh, nullptr, nullptr, scaleQ, L_TOK, nullptr,
        L_TOK, C_DIM, C_DIM, 0);
    gemm_bf16_kernel<128, false><<<gKVc, 256, GEMM_SMEM(128, false)>>>(
        ctx, cwkv2, nullptr, nullptr, nullptr, nullptr, 0,
        k2h, v2h, nullptr, 1.f, LCTXP, nullptr,
        LCTX, 2 * C_DIM, CTX_DIM, 0);
    attn_reg_kernel<<<attnGrid, 256, ATTN_SMEM>>>(qh, k2h, v2h, a, LCTX, LCTXP);
    gemm_bf16_kernel<64, false><<<g320s, 256, GEMM_SMEM(64, false)>>>(
        a, cwo2, bo2, t, t, nullptr, 0,
        nullptr, nullptr, nullptr, 0.f, 0, nullptr,
        L_TOK, C_DIM, C_DIM, 0);

    // ---- feed-forward ----
    ln_kernel<<<L_TOK / 8, 256>>>(t, ln3_w, ln3_b, hn);
    gemm_bf16_kernel<128, true><<<gFF1, 256, GEMM_SMEM(128, true)>>>(
        hn, cwff1, bff1, nullptr, nullptr, nullptr, 0,
        nullptr, nullptr, nullptr, 0.f, 0, gg,
        L_TOK, 2 * FFI, C_DIM, 0);
    gemm_bf16_kernel<64, false><<<g320s, 256, GEMM_SMEM(64, false)>>>(
        gg, cwff2, bff2, t, t, tb, C_DIM,
        nullptr, nullptr, nullptr, 0.f, 0, nullptr,
        L_TOK, C_DIM, FFI, 0);

    // ---- proj_out (+ x residual), channel-major store ----
    gemm_bf16_kernel<64, false><<<g320s, 256, GEMM_SMEM(64, false)>>>(
        tb, cwout, b_out, x, out, nullptr, 0,
        nullptr, nullptr, nullptr, 0.f, 0, nullptr,
        L_TOK, C_DIM, C_DIM, 1);
}

// round 17
// speedup vs baseline: 1.0245x; 1.0245x over previous
#include <cuda_runtime.h>
#include <cuda_bf16.h>
#include <mma.h>
#include <math.h>
#include <cstdint>

using namespace nvcuda;

// ---------------------------------------------------------------------------
// SpatialTransformer — round 16: revert MT=64 (issue-bound, not occ-bound),
// MT=128 everywhere; side-stream overlap for wqkv compose + ctx K/V proj
// (graph fork/join via events). Rest as round 14.
// ---------------------------------------------------------------------------

#define L_TOK   4096
#define C_DIM   320
#define HEADS   8
#define DH      40
#define DHP     48
#define CTX_DIM 768
#define LCTX    77
#define LCTXP   128
#define FFI     1280
#define NGROUPS 32
#define CH_PER_G 10

typedef __nv_bfloat16 bf16;

// fp32 scratch
__device__ float g_t [L_TOK * C_DIM];
__device__ float g_part[NGROUPS * 8 * 2];
// bf16 activations (zero-initialized; pad lanes never written)
__device__ bf16 b_xn[L_TOK * C_DIM];
__device__ bf16 b_hn[L_TOK * C_DIM];
__device__ bf16 b_a [L_TOK * C_DIM];
__device__ bf16 b_gg[L_TOK * FFI];
__device__ bf16 b_t [L_TOK * C_DIM];
__device__ bf16 b_qh[HEADS * L_TOK * DHP];
__device__ bf16 b_kh[HEADS * L_TOK * DHP];
__device__ bf16 b_vh[HEADS * L_TOK * DHP];
__device__ bf16 b_k2h[HEADS * LCTXP * DHP];
__device__ bf16 b_v2h[HEADS * LCTXP * DHP];
__device__ bf16 b_ctx[LCTX * CTX_DIM];
// bf16 weights
__device__ bf16 b_w_in[C_DIM * C_DIM];
__device__ bf16 b_wq1[C_DIM * C_DIM];
__device__ bf16 b_wkv1[C_DIM * 2 * C_DIM];
__device__ bf16 b_wqkv1[C_DIM * 3 * C_DIM];
__device__ bf16 b_wo1[C_DIM * C_DIM];
__device__ bf16 b_wq2[C_DIM * C_DIM];
__device__ bf16 b_wkv2[CTX_DIM * 2 * C_DIM];
__device__ bf16 b_wo2[C_DIM * C_DIM];
__device__ bf16 b_wff1[C_DIM * 2 * FFI];
__device__ bf16 b_wff2[FFI * C_DIM];
__device__ bf16 b_wout[C_DIM * C_DIM];

// ---------------- helpers ----------------
__device__ __forceinline__ unsigned int smem_u32(const void* p)
{ return (unsigned int)__cvta_generic_to_shared(p); }

__device__ __forceinline__ void cp16(unsigned int dst, const void* src, int sz)
{ asm volatile("cp.async.cg.shared.global [%0], [%1], 16, %2;\n"
               :: "r"(dst), "l"(src), "r"(sz)); }

__device__ __forceinline__ void cp_commit()
{ asm volatile("cp.async.commit_group;\n"); }

template<int N> __device__ __forceinline__ void cp_wait()
{ asm volatile("cp.async.wait_group %0;\n" :: "n"(N)); }

__device__ __forceinline__ float ex2(float x)
{ float r; asm("ex2.approx.f32 %0, %1;" : "=f"(r) : "f"(x)); return r; }

__device__ __forceinline__ void mma16816(float* c,
    unsigned a0, unsigned a1, unsigned a2, unsigned a3,
    unsigned b0, unsigned b1)
{
    asm volatile(
        "mma.sync.aligned.m16n8k16.row.col.f32.bf16.bf16.f32 "
        "{%0,%1,%2,%3}, {%4,%5,%6,%7}, {%8,%9}, {%0,%1,%2,%3};"
        : "+f"(c[0]), "+f"(c[1]), "+f"(c[2]), "+f"(c[3])
        : "r"(a0), "r"(a1), "r"(a2), "r"(a3), "r"(b0), "r"(b1));
}

__device__ __forceinline__ void mma16808(float* c,
    unsigned a0, unsigned a1, unsigned b0)
{
    asm volatile(
        "mma.sync.aligned.m16n8k8.row.col.f32.bf16.bf16.f32 "
        "{%0,%1,%2,%3}, {%4,%5}, {%6}, {%0,%1,%2,%3};"
        : "+f"(c[0]), "+f"(c[1]), "+f"(c[2]), "+f"(c[3])
        : "r"(a0), "r"(a1), "r"(b0));
}

// ---------------- fused prep ----------------
struct CvtJobs {
    const float4* s[9];
    __nv_bfloat162* d[9];
    int n[9];
};

__global__ __launch_bounds__(256) void prep_kernel(
    CvtJobs J,
    const float4* wk1, const float4* wv1, __nv_bfloat162* dkv1,
    const float4* wk2, const float4* wv2, __nv_bfloat162* dkv2,
    const float4* wq1f, __nv_bfloat162* dqkv1,
    const float* __restrict__ x)
{
    int i0 = blockIdx.x * blockDim.x + threadIdx.x;
    int st = gridDim.x * blockDim.x;
    #pragma unroll
    for (int q = 0; q < 9; q++) {
        const float4* s = J.s[q];
        __nv_bfloat162* d = J.d[q];
        int n = J.n[q];
        for (int j = i0; j < n; j += st) {
            float4 v = s[j];
            d[2*j]   = __floats2bfloat162_rn(v.x, v.y);
            d[2*j+1] = __floats2bfloat162_rn(v.z, v.w);
        }
    }
    const int C4 = C_DIM / 4;
    {
        int n4 = C_DIM * C4;
        for (int j = i0; j < n4; j += st) {
            int k = j / C4, c4 = j % C4;
            float4 a = wk1[j];
            float4 b = wv1[j];
            __nv_bfloat162* row = dkv1 + k * C_DIM;
            row[c4*2]   = __floats2bfloat162_rn(a.x, a.y);
            row[c4*2+1] = __floats2bfloat162_rn(a.z, a.w);
            row[C_DIM/2 + c4*2]   = __floats2bfloat162_rn(b.x, b.y);
            row[C_DIM/2 + c4*2+1] = __floats2bfloat162_rn(b.z, b.w);
        }
    }
    {
        int n4 = C_DIM * C4;
        for (int j = i0; j < n4; j += st) {
            int k = j / C4, c4 = j % C4;
            float4 a = wq1f[j];
            __nv_bfloat162* row = dqkv1 + k * (3 * C_DIM / 2);
            row[c4*2]   = __floats2bfloat162_rn(a.x, a.y);
            row[c4*2+1] = __floats2bfloat162_rn(a.z, a.w);
        }
    }
    {
        int n4 = CTX_DIM * C4;
        for (int j = i0; j < n4; j += st) {
            int k = j / C4, c4 = j % C4;
            float4 a = wk2[j];
            float4 b = wv2[j];
            __nv_bfloat162* row = dkv2 + k * C_DIM;
            row[c4*2]   = __floats2bfloat162_rn(a.x, a.y);
            row[c4*2+1] = __floats2bfloat162_rn(a.z, a.w);
            row[C_DIM/2 + c4*2]   = __floats2bfloat162_rn(b.x, b.y);
            row[C_DIM/2 + c4*2+1] = __floats2bfloat162_rn(b.z, b.w);
        }
    }
    if (blockIdx.x < 256) {
        int b = blockIdx.x;
        int g = b >> 3, seg = b & 7;
        int tid = threadIdx.x;
        const int SEG4 = CH_PER_G * L_TOK / 4 / 8;
        const float4* base = (const float4*)(x + (size_t)g * CH_PER_G * L_TOK)
                             + seg * SEG4;
        float s = 0.f, ss = 0.f;
        for (int i = tid; i < SEG4; i += 256) {
            float4 v = base[i];
            s  += v.x + v.y + v.z + v.w;
            ss += v.x*v.x + v.y*v.y + v.z*v.z + v.w*v.w;
        }
        __shared__ float rs[256], rss[256];
        rs[tid] = s; rss[tid] = ss;
        __syncthreads();
        for (int o = 128; o > 0; o >>= 1) {
            if (tid < o) { rs[tid] += rs[tid + o]; rss[tid] += rss[tid + o]; }
            __syncthreads();
        }
        if (tid == 0) {
            g_part[b * 2]     = rs[0];
            g_part[b * 2 + 1] = rss[0];
        }
    }
}

// ---------------- GroupNorm apply ----------------
__global__ void gn_apply_kernel(const float* __restrict__ x,
                                const float* __restrict__ gw,
                                const float* __restrict__ gb,
                                bf16* __restrict__ out)
{
    __shared__ float tile[32][65];
    __shared__ float smean[NGROUPS], srstd[NGROUPS];
    if (threadIdx.x < NGROUPS) {
        int g = threadIdx.x;
        float s = 0.f, ss = 0.f;
        #pragma unroll
        for (int k = 0; k < 8; k++) {
            s  += g_part[(g * 8 + k) * 2];
            ss += g_part[(g * 8 + k) * 2 + 1];
        }
        const float NEL = (float)(CH_PER_G * L_TOK);
        float m = s / NEL;
        float var = ss / NEL - m * m;
        smean[g] = m;
        srstd[g] = rsqrtf(var + 1e-6f);
    }
    __syncthreads();

    int hw0 = blockIdx.x * 64;
    int c0  = blockIdx.y * 32;
    #pragma unroll
    for (int p = 0; p < 8; p++) {
        int i = threadIdx.x + p * 256;
        int c = i >> 6, hw = i & 63;
        int gc = c0 + c;
        int g = gc / CH_PER_G;
        float v = (x[(size_t)gc * L_TOK + hw0 + hw] - smean[g]) * srstd[g]
                  * gw[gc] + gb[gc];
        tile[c][hw] = v;
    }
    __syncthreads();
    #pragma unroll
    for (int p = 0; p < 8; p++) {
        int i = threadIdx.x + p * 256;
        int hw = i >> 5, c = i & 31;
        out[(size_t)(hw0 + hw) * C_DIM + c0 + c] = __float2bfloat16(tile[c][hw]);
    }
}

// ---------------- LayerNorm ----------------
__global__ __launch_bounds__(256) void ln_kernel(
    const float* __restrict__ in, const float* __restrict__ w,
    const float* __restrict__ b, bf16* __restrict__ out)
{
    int token = blockIdx.x * 8 + (threadIdx.x >> 5);
    int lane = threadIdx.x & 31;
    const float4* row4 = (const float4*)(in + (size_t)token * C_DIM);
    float s = 0.f, ss = 0.f;
    float4 va[3];
    #pragma unroll
    for (int j = 0; j < 3; j++) {
        int idx = lane + j * 32;
        if (idx < 80) {
            float4 v = row4[idx];
            va[j] = v;
            s  += v.x + v.y + v.z + v.w;
            ss += v.x*v.x + v.y*v.y + v.z*v.z + v.w*v.w;
        }
    }
    #pragma unroll
    for (int o = 16; o > 0; o >>= 1) {
        s  += __shfl_xor_sync(0xffffffffu, s, o);
        ss += __shfl_xor_sync(0xffffffffu, ss, o);
    }
    float m = s / (float)C_DIM;
    float var = ss / (float)C_DIM - m * m;
    float r = rsqrtf(var + 1e-5f);

    const float4* w4 = (const float4*)w;
    const float4* b4 = (const float4*)b;
    __nv_bfloat162* o2 = (__nv_bfloat162*)(out + (size_t)token * C_DIM);
    #pragma unroll
    for (int j = 0; j < 3; j++) {
        int idx = lane + j * 32;
        if (idx < 80) {
            float4 v = va[j];
            float4 ww = w4[idx];
            float4 bb = b4[idx];
            o2[idx * 2]     = __floats2bfloat162_rn((v.x - m) * r * ww.x + bb.x,
                                                    (v.y - m) * r * ww.y + bb.y);
            o2[idx * 2 + 1] = __floats2bfloat162_rn((v.z - m) * r * ww.z + bb.z,
                                                    (v.w - m) * r * ww.w + bb.w);
        }
    }
}

// ---------------- bf16 TC GEMM, 128x64, 256 thr, 3-stage, DUAL templated ---
template<bool DUAL> struct GemmBufT {
    bf16 As[3][128][40];
    bf16 Bs[3][DUAL ? 2 : 1][32][72];
};
#define GEMM_SMEM_S ((int)sizeof(GemmBufT<false>))
#define GEMM_SMEM_D ((int)sizeof(GemmBufT<true>))

template<bool DUAL>
__global__ __launch_bounds__(256) void gemm_bf16_kernel(
    const bf16* __restrict__ A, const bf16* __restrict__ B,
    const float* __restrict__ bias, const float* __restrict__ res,
    float* __restrict__ Cf, bf16* __restrict__ Cbf, int ldcBf,
    bf16* __restrict__ dst0, bf16* __restrict__ dst1, bf16* __restrict__ dst2,
    float scale0, int Lpad,
    bf16* __restrict__ ggOut,
    int M, int N, int K, int transOut)
{
    extern __shared__ char smraw[];
    GemmBufT<DUAL>* in = (GemmBufT<DUAL>*)smraw;
    float (*Cs)[68] = (float(*)[68])smraw;

    int bm = blockIdx.y * 128;
    int bn = blockIdx.x * 64;
    int tid = threadIdx.x;
    int w = tid >> 5, wm = w >> 1, wn = w & 1;

    wmma::fragment<wmma::accumulator, 16, 16, 16, float> acc[2][2];
    wmma::fragment<wmma::accumulator, 16, 16, 16, float> acc2[DUAL ? 2 : 1][2];
    #pragma unroll
    for (int i = 0; i < 2; i++)
        #pragma unroll
        for (int j = 0; j < 2; j++) wmma::fill_fragment(acc[i][j], 0.f);
    if (DUAL) {
        #pragma unroll
        for (int i = 0; i < 2; i++)
            #pragma unroll
            for (int j = 0; j < 2; j++) wmma::fill_fragment(acc2[i][j], 0.f);
    }

    auto issue = [&](int s, int k0) {
        #pragma unroll
        for (int p = 0; p < 2; p++) {
            int c = tid + p * 256;
            int row = c >> 2, ch = c & 3;
            int gm = bm + row;
            const bf16* src = A + (size_t)(gm < M ? gm : 0) * K + k0 + ch * 8;
            cp16(smem_u32(&in->As[s][row][ch * 8]), src, (gm < M) ? 16 : 0);
        }
        {
            int row = tid >> 3, ch = tid & 7;
            const bf16* src = B + (size_t)(k0 + row) * N + bn + ch * 8;
            cp16(smem_u32(&in->Bs[s][0][row][ch * 8]), src, 16);
            if (DUAL)
                cp16(smem_u32(&in->Bs[s][DUAL ? 1 : 0][row][ch * 8]), src + FFI, 16);
        }
        cp_commit();
    };

    int nk = K / 32;
    issue(0, 0);
    issue(1, 32);
    for (int ki = 0; ki < nk; ki++) {
        int s = ki - (ki / 3) * 3;
        if (ki == nk - 1) cp_wait<0>(); else cp_wait<1>();
        __syncthreads();
        #pragma unroll
        for (int ks = 0; ks < 2; ks++) {
            wmma::fragment<wmma::matrix_a, 16, 16, 16, bf16, wmma::row_major> af[2];
            wmma::fragment<wmma::matrix_b, 16, 16, 16, bf16, wmma::row_major> bfr[2];
            wmma::load_matrix_sync(af[0], &in->As[s][wm*32     ][ks*16], 40);
            wmma::load_matrix_sync(af[1], &in->As[s][wm*32 + 16][ks*16], 40);
            wmma::load_matrix_sync(bfr[0], &in->Bs[s][0][ks*16][wn*32     ], 72);
            wmma::load_matrix_sync(bfr[1], &in->Bs[s][0][ks*16][wn*32 + 16], 72);
            #pragma unroll
            for (int i = 0; i < 2; i++)
                #pragma unroll
                for (int j = 0; j < 2; j++)
                    wmma::mma_sync(acc[i][j], af[i], bfr[j], acc[i][j]);
            if (DUAL) {
                wmma::load_matrix_sync(bfr[0], &in->Bs[s][DUAL?1:0][ks*16][wn*32     ], 72);
                wmma::load_matrix_sync(bfr[1], &in->Bs[s][DUAL?1:0][ks*16][wn*32 + 16], 72);
                #pragma unroll
                for (int i = 0; i < 2; i++)
                    #pragma unroll
                    for (int j = 0; j < 2; j++)
                        wmma::mma_sync(acc2[i][j], af[i], bfr[j], acc2[i][j]);
            }
        }
        if (ki + 2 < nk) {
            int s2 = (ki + 2) - ((ki + 2) / 3) * 3;
            issue(s2, (ki + 2) * 32);
        }
    }
    __syncthreads();

    // ---- epilogue ----
    #pragma unroll
    for (int i = 0; i < 2; i++)
        #pragma unroll
        for (int j = 0; j < 2; j++)
            wmma::store_matrix_sync(&Cs[wm*32 + i*16][wn*32 + j*16],
                                    acc[i][j], 68, wmma::mem_row_major);
    __syncthreads();

    if (DUAL) {
        float rA[32];
        #pragma unroll
        for (int p = 0; p < 32; p++) {
            int i = tid + p * 256;
            rA[p] = Cs[i >> 6][i & 63];
        }
        __syncthreads();
        #pragma unroll
        for (int i = 0; i < 2; i++)
            #pragma unroll
            for (int j = 0; j < 2; j++)
                wmma::store_matrix_sync(&Cs[wm*32 + i*16][wn*32 + j*16],
                                        acc2[i][j], 68, wmma::mem_row_major);
        __syncthreads();
        #pragma unroll
        for (int p = 0; p < 32; p++) {
            int i = tid + p * 256;
            int m = i >> 6, n = i & 63;
            int gm = bm + m, gn = bn + n;
            float av = rA[p] + bias[gn];
            float gv = Cs[m][n] + bias[gn + FFI];
            float ge = 0.5f * gv * (1.f + erff(gv * 0.70710678118654752f));
            ggOut[(size_t)gm * FFI + gn] = __float2bfloat16(av * ge);
        }
        return;
    }

    if (transOut) {
        #pragma unroll
        for (int p = 0; p < 32; p++) {
            int i = tid + p * 256;
            int m = i & 127, n = i >> 7;
            int gm = bm + m, gn = bn + n;
            float v = Cs[m][n];
            if (bias) v += bias[gn];
            size_t idx = (size_t)gn * M + gm;
            if (res) v += res[idx];
            Cf[idx] = v;
        }
        return;
    }

    #pragma unroll
    for (int p = 0; p < 32; p++) {
        int i = tid + p * 256;
        int m = i >> 6, n = i & 63;
        int gm = bm + m, gn = bn + n;
        if (gm >= M) continue;
        float v = Cs[m][n];
        if (bias) v += bias[gn];
        if (Cf) {
            size_t idx = (size_t)gm * N + gn;
            if (res) v += res[idx];
            Cf[idx] = v;
        }
        if (Cbf) Cbf[(size_t)gm * ldcBf + gn] = __float2bfloat16(v);
        if (dst0) {
            int which = gn / C_DIM;
            int cc = gn - which * C_DIM;
            bf16* d = (which == 0) ? dst0 : ((which == 1) ? dst1 : dst2);
            float sc = (which == 0) ? scale0 : 1.f;
            int h = cc & 7, j = cc >> 3;
            d[((size_t)h * Lpad + gm) * DHP + j] = __float2bfloat16(v * sc);
        }
    }
}

// ---------------- FA2 attention, exact dh=40 ----------------
#define ATTN_SMEM (3 * 3072 * 2 * 2 + 128 * 48 * 2)   // 49152

__global__ __launch_bounds__(256, 2) void attn_reg_kernel(
    const bf16* __restrict__ qh, const bf16* __restrict__ kh,
    const bf16* __restrict__ vh, bf16* __restrict__ Obf,
    int Lk, int Lpad)
{
    extern __shared__ char smraw[];
    bf16* sK = (bf16*)smraw;
    bf16* sV = sK + 3 * 3072;
    bf16* sQ = sV + 3 * 3072;

    int h = blockIdx.y;
    int qbase = blockIdx.x * 128;
    int tid = threadIdx.x, w = tid >> 5, lane = tid & 31;
    int r0 = lane >> 2, cq = (lane & 3) * 2;

    auto load_kv = [&](int s, int k0) {
        const bf16* kp = kh + ((size_t)h * Lpad + k0) * DHP;
        const bf16* vp = vh + ((size_t)h * Lpad + k0) * DHP;
        #pragma unroll
        for (int p = 0; p < 3; p++) {
            int c = tid + p * 256;
            if (c < 384) cp16(smem_u32(&sK[s * 3072 + c * 8]), kp + c * 8, 16);
            else         cp16(smem_u32(&sV[s * 3072 + (c - 384) * 8]),
                              vp + (c - 384) * 8, 16);
        }
        cp_commit();
    };

    int ntiles = (Lk + 63) / 64;
    load_kv(0, 0);
    if (ntiles > 1) load_kv(1, 64);

    {
        const uint4* src = (const uint4*)(qh + ((size_t)h * L_TOK + qbase) * DHP);
        uint4* dst = (uint4*)sQ;
        #pragma unroll
        for (int p = 0; p < 3; p++) dst[tid + p * 256] = src[tid + p * 256];
    }
    __syncthreads();

    unsigned qa[2][4], qa8[2];
    {
        const bf16* qrow = sQ + (w * 16 + r0) * 48;
        #pragma unroll
        for (int kd = 0; kd < 2; kd++) {
            qa[kd][0] = *(const unsigned*)(qrow + kd * 16 + cq);
            qa[kd][1] = *(const unsigned*)(qrow + 8 * 48 + kd * 16 + cq);
            qa[kd][2] = *(const unsigned*)(qrow + kd * 16 + 8 + cq);
            qa[kd][3] = *(const unsigned*)(qrow + 8 * 48 + kd * 16 + 8 + cq);
        }
        qa8[0] = *(const unsigned*)(qrow + 32 + cq);
        qa8[1] = *(const unsigned*)(qrow + 8 * 48 + 32 + cq);
    }

    float O[5][4] = {};
    float m0 = -1e30f, m1 = -1e30f, l0 = 0.f, l1 = 0.f;

    for (int ti = 0; ti < ntiles; ti++) {
        int s = ti - (ti / 3) * 3;
        int k0 = ti * 64;
        if (ti == ntiles - 1) cp_wait<0>(); else cp_wait<1>();
        __syncthreads();

        float S[8][4];
        #pragma unroll
        for (int j = 0; j < 8; j++)
            S[j][0] = S[j][1] = S[j][2] = S[j][3] = 0.f;
        #pragma unroll
        for (int j = 0; j < 8; j++) {
            const bf16* kb = &sK[s * 3072 + (j * 8 + r0) * 48];
            #pragma unroll
            for (int kd = 0; kd < 2; kd++) {
                unsigned b0 = *(const unsigned*)(kb + kd * 16 + cq);
                unsigned b1 = *(const unsigned*)(kb + kd * 16 + 8 + cq);
                mma16816(S[j], qa[kd][0], qa[kd][1], qa[kd][2], qa[kd][3], b0, b1);
            }
            unsigned b8 = *(const unsigned*)(kb + 32 + cq);
            mma16808(S[j], qa8[0], qa8[1], b8);
        }

        if (k0 + 64 > Lk) {
            #pragma unroll
            for (int j = 0; j < 8; j++) {
                int col = k0 + j * 8 + cq;
                if (col >= Lk)     { S[j][0] = -1e30f; S[j][2] = -1e30f; }
                if (col + 1 >= Lk) { S[j][1] = -1e30f; S[j][3] = -1e30f; }
            }
        }

        float mx0 = -1e30f, mx1 = -1e30f;
        #pragma unroll
        for (int j = 0; j < 8; j++) {
            mx0 = fmaxf(mx0, fmaxf(S[j][0], S[j][1]));
            mx1 = fmaxf(mx1, fmaxf(S[j][2], S[j][3]));
        }
        mx0 = fmaxf(mx0, __shfl_xor_sync(0xffffffffu, mx0, 1));
        mx0 = fmaxf(mx0, __shfl_xor_sync(0xffffffffu, mx0, 2));
        mx1 = fmaxf(mx1, __shfl_xor_sync(0xffffffffu, mx1, 1));
        mx1 = fmaxf(mx1, __shfl_xor_sync(0xffffffffu, mx1, 2));

        float mn0 = fmaxf(m0, mx0), mn1 = fmaxf(m1, mx1);
        float corr0 = ex2(m0 - mn0), corr1 = ex2(m1 - mn1);
        m0 = mn0; m1 = mn1;

        unsigned P[8][2];
        float sum0 = 0.f, sum1 = 0.f;
        #pragma unroll
        for (int j = 0; j < 8; j++) {
            float p0 = ex2(S[j][0] - mn0), p1 = ex2(S[j][1] - mn0);
            float p2 = ex2(S[j][2] - mn1), p3 = ex2(S[j][3] - mn1);
            sum0 += p0 + p1; sum1 += p2 + p3;
            __nv_bfloat162 u0 = __floats2bfloat162_rn(p0, p1);
            __nv_bfloat162 u1 = __floats2bfloat162_rn(p2, p3);
            P[j][0] = *(unsigned*)&u0;
            P[j][1] = *(unsigned*)&u1;
        }
        sum0 += __shfl_xor_sync(0xffffffffu, sum0, 1);
        sum0 += __shfl_xor_sync(0xffffffffu, sum0, 2);
        sum1 += __shfl_xor_sync(0xffffffffu, sum1, 1);
        sum1 += __shfl_xor_sync(0xffffffffu, sum1, 2);
        l0 = l0 * corr0 + sum0;
        l1 = l1 * corr1 + sum1;

        #pragma unroll
        for (int jd = 0; jd < 5; jd++) {
            O[jd][0] *= corr0; O[jd][1] *= corr0;
            O[jd][2] *= corr1; O[jd][3] *= corr1;
        }

        #pragma unroll
        for (int t = 0; t < 4; t++) {
            int g = lane >> 3;
            #pragma unroll
            for (int p2 = 0; p2 < 2; p2++) {
                unsigned addr = smem_u32(
                    &sV[s * 3072 + (t * 16 + (g & 1) * 8 + (lane & 7)) * 48
                        + p2 * 16 + (g >> 1) * 8]);
                unsigned v0, v1, v2, v3;
                asm volatile(
                    "ldmatrix.sync.aligned.m8n8.x4.trans.shared.b16 "
                    "{%0,%1,%2,%3}, [%4];"
                    : "=r"(v0), "=r"(v1), "=r"(v2), "=r"(v3) : "r"(addr));
                mma16816(O[2*p2],   P[2*t][0], P[2*t][1],
                                    P[2*t+1][0], P[2*t+1][1], v0, v1);
                mma16816(O[2*p2+1], P[2*t][0], P[2*t][1],
                                    P[2*t+1][0], P[2*t+1][1], v2, v3);
            }
            {
                unsigned addr = smem_u32(
                    &sV[s * 3072 + (t * 16 + ((lane >> 3) & 1) * 8 + (lane & 7)) * 48
                        + 32]);
                unsigned v0, v1;
                asm volatile(
                    "ldmatrix.sync.aligned.m8n8.x2.trans.shared.b16 "
                    "{%0,%1}, [%2];"
                    : "=r"(v0), "=r"(v1) : "r"(addr));
                mma16816(O[4], P[2*t][0], P[2*t][1],
                               P[2*t+1][0], P[2*t+1][1], v0, v1);
            }
        }

        if (ti + 2 < ntiles) {
            int s2 = (ti + 2) - ((ti + 2) / 3) * 3;
            load_kv(s2, (ti + 2) * 64);
        }
    }

    float il0 = 1.f / l0, il1 = 1.f / l1;
    int tok = qbase + w * 16 + r0;
    #pragma unroll
    for (int jd = 0; jd < 5; jd++) {
        int col = jd * 8 + cq;
        __nv_bfloat162 o0 = __floats2bfloat162_rn(O[jd][0] * il0, O[jd][1] * il0);
        __nv_bfloat162 o1 = __floats2bfloat162_rn(O[jd][2] * il1, O[jd][3] * il1);
        *(__nv_bfloat162*)(Obf + (size_t)tok * C_DIM + h * DH + col) = o0;
        *(__nv_bfloat162*)(Obf + (size_t)(tok + 8) * C_DIM + h * DH + col) = o1;
    }
}

// ---------------------------------------------------------------------------
extern "C" void kernel_launch(void* const* d_in, const int* in_sizes, int n_in,
                              void* d_out, int out_size)
{
    const float* x       = (const float*)d_in[0];
    const float* context = (const float*)d_in[1];
    const float* gn_w    = (const float*)d_in[2];
    const float* gn_b    = (const float*)d_in[3];
    const float* w_in    = (const float*)d_in[4];
    const float* b_in    = (const float*)d_in[5];
    const float* ln1_w   = (const float*)d_in[6];
    const float* ln1_b   = (const float*)d_in[7];
    const float* wq1     = (const float*)d_in[8];
    const float* wk1     = (const float*)d_in[9];
    const float* wv1     = (const float*)d_in[10];
    const float* wo1     = (const float*)d_in[11];
    const float* bo1     = (const float*)d_in[12];
    const float* ln2_w   = (const float*)d_in[13];
    const float* ln2_b   = (const float*)d_in[14];
    const float* wq2     = (const float*)d_in[15];
    const float* wk2     = (const float*)d_in[16];
    const float* wv2     = (const float*)d_in[17];
    const float* wo2     = (const float*)d_in[18];
    const float* bo2     = (const float*)d_in[19];
    const float* ln3_w   = (const float*)d_in[20];
    const float* ln3_b   = (const float*)d_in[21];
    const float* wff1    = (const float*)d_in[22];
    const float* bff1    = (const float*)d_in[23];
    const float* wff2    = (const float*)d_in[24];
    const float* bff2    = (const float*)d_in[25];
    const float* w_out   = (const float*)d_in[26];
    const float* b_out   = (const float*)d_in[27];
    float* out = (float*)d_out;

    static float *t = nullptr;
    static bf16 *xn, *hn, *a, *gg, *tb, *qh, *kh, *vh, *k2h, *v2h, *ctx;
    static bf16 *cw_in, *cwq1, *cwkv1, *cwqkv1, *cwo1, *cwq2, *cwkv2, *cwo2,
                *cwff1, *cwff2, *cwout;
    static cudaStream_t s1;
    static cudaEvent_t e0, e1;
    static bool init_done = false;
    if (!init_done) {
        cudaGetSymbolAddress((void**)&t,  g_t);
        cudaGetSymbolAddress((void**)&xn, b_xn);
        cudaGetSymbolAddress((void**)&hn, b_hn);
        cudaGetSymbolAddress((void**)&a,  b_a);
        cudaGetSymbolAddress((void**)&gg, b_gg);
        cudaGetSymbolAddress((void**)&tb, b_t);
        cudaGetSymbolAddress((void**)&qh, b_qh);
        cudaGetSymbolAddress((void**)&kh, b_kh);
        cudaGetSymbolAddress((void**)&vh, b_vh);
        cudaGetSymbolAddress((void**)&k2h, b_k2h);
        cudaGetSymbolAddress((void**)&v2h, b_v2h);
        cudaGetSymbolAddress((void**)&ctx, b_ctx);
        cudaGetSymbolAddress((void**)&cw_in, b_w_in);
        cudaGetSymbolAddress((void**)&cwq1, b_wq1);
        cudaGetSymbolAddress((void**)&cwkv1, b_wkv1);
        cudaGetSymbolAddress((void**)&cwqkv1, b_wqkv1);
        cudaGetSymbolAddress((void**)&cwo1, b_wo1);
        cudaGetSymbolAddress((void**)&cwq2, b_wq2);
        cudaGetSymbolAddress((void**)&cwkv2, b_wkv2);
        cudaGetSymbolAddress((void**)&cwo2, b_wo2);
        cudaGetSymbolAddress((void**)&cwff1, b_wff1);
        cudaGetSymbolAddress((void**)&cwff2, b_wff2);
        cudaGetSymbolAddress((void**)&cwout, b_wout);
        cudaFuncSetAttribute(gemm_bf16_kernel<false>,
                             cudaFuncAttributeMaxDynamicSharedMemorySize,
                             GEMM_SMEM_S);
        cudaFuncSetAttribute(gemm_bf16_kernel<true>,
                             cudaFuncAttributeMaxDynamicSharedMemorySize,
                             GEMM_SMEM_D);
        cudaFuncSetAttribute(attn_reg_kernel,
                             cudaFuncAttributeMaxDynamicSharedMemorySize,
                             ATTN_SMEM);
        cudaStreamCreateWithFlags(&s1, cudaStreamNonBlocking);
        cudaEventCreateWithFlags(&e0, cudaEventDisableTiming);
        cudaEventCreateWithFlags(&e1, cudaEventDisableTiming);
        init_done = true;
    }

    const float scaleQ = 0.15811388300841898f * 1.4426950408889634f;
    const int CC4 = C_DIM * C_DIM / 4;

    CvtJobs J;
    J.s[0] = (const float4*)context; J.d[0] = (__nv_bfloat162*)ctx;   J.n[0] = LCTX * CTX_DIM / 4;
    J.s[1] = (const float4*)w_in;    J.d[1] = (__nv_bfloat162*)cw_in; J.n[1] = CC4;
    J.s[2] = (const float4*)wq1;     J.d[2] = (__nv_bfloat162*)cwq1;  J.n[2] = CC4;
    J.s[3] = (const float4*)wo1;     J.d[3] = (__nv_bfloat162*)cwo1;  J.n[3] = CC4;
    J.s[4] = (const float4*)wq2;     J.d[4] = (__nv_bfloat162*)cwq2;  J.n[4] = CC4;
    J.s[5] = (const float4*)wo2;     J.d[5] = (__nv_bfloat162*)cwo2;  J.n[5] = CC4;
    J.s[6] = (const float4*)wff1;    J.d[6] = (__nv_bfloat162*)cwff1; J.n[6] = C_DIM * 2 * FFI / 4;
    J.s[7] = (const float4*)wff2;    J.d[7] = (__nv_bfloat162*)cwff2; J.n[7] = FFI * C_DIM / 4;
    J.s[8] = (const float4*)w_out;   J.d[8] = (__nv_bfloat162*)cwout; J.n[8] = CC4;
    prep_kernel<<<512, 256>>>(J,
        (const float4*)wk1, (const float4*)wv1, (__nv_bfloat162*)cwkv1,
        (const float4*)wk2, (const float4*)wv2, (__nv_bfloat162*)cwkv2,
        (const float4*)wq1, (__nv_bfloat162*)cwqkv1,
        x);

    // ---- fork: compose wqkv + ctx K/V projection on side stream ----
    cudaEventRecord(e0, 0);
    cudaStreamWaitEvent(s1, e0, 0);
    {
        dim3 gComp(2 * C_DIM / 64, (C_DIM + 127) / 128);   // (10, 3)
        gemm_bf16_kernel<false><<<gComp, 256, GEMM_SMEM_S, s1>>>(
            cwq1, cwkv1, nullptr, nullptr, nullptr,
            cwqkv1 + C_DIM, 3 * C_DIM,
            nullptr, nullptr, nullptr, 0.f, 0, nullptr,
            C_DIM, 2 * C_DIM, C_DIM, 0);
        dim3 gKVc(2 * C_DIM / 64, 1);
        gemm_bf16_kernel<false><<<gKVc, 256, GEMM_SMEM_S, s1>>>(
            ctx, cwkv2, nullptr, nullptr, nullptr, nullptr, 0,
            k2h, v2h, nullptr, 1.f, LCTXP, nullptr,
            LCTX, 2 * C_DIM, CTX_DIM, 0);
    }
    cudaEventRecord(e1, s1);

    dim3 g320(C_DIM / 64, L_TOK / 128);
    dim3 gQKV(3 * C_DIM / 64, L_TOK / 128);   // (15, 32)
    dim3 gFF1(FFI / 64, L_TOK / 128);
    dim3 attnGrid(L_TOK / 128, HEADS);

    gn_apply_kernel<<<dim3(L_TOK / 64, C_DIM / 32), 256>>>(x, gn_w, gn_b, xn);
    gemm_bf16_kernel<false><<<g320, 256, GEMM_SMEM_S>>>(
        xn, cw_in, b_in, nullptr, t, nullptr, 0,
        nullptr, nullptr, nullptr, 0.f, 0, nullptr,
        L_TOK, C_DIM, C_DIM, 0);

    // ---- self-attention: LN -> fused QKV GEMM -> attn -> out-proj ----
    // (QKV GEMM needs composed wqkv1 from side stream)
    cudaStreamWaitEvent(0, e1, 0);
    ln_kernel<<<L_TOK / 8, 256>>>(t, ln1_w, ln1_b, hn);
    gemm_bf16_kernel<false><<<gQKV, 256, GEMM_SMEM_S>>>(
        hn, cwqkv1, nullptr, nullptr, nullptr, nullptr, 0,
        qh, kh, vh, scaleQ, L_TOK, nullptr,
        L_TOK, 3 * C_DIM, C_DIM, 0);
    attn_reg_kernel<<<attnGrid, 256, ATTN_SMEM>>>(qh, kh, vh, a, L_TOK, L_TOK);
    gemm_bf16_kernel<false><<<g320, 256, GEMM_SMEM_S>>>(
        a, cwo1, bo1, t, t, nullptr, 0,
        nullptr, nullptr, nullptr, 0.f, 0, nullptr,
        L_TOK, C_DIM, C_DIM, 0);

    // ---- cross-attention (k2h/v2h already computed on side stream) ----
    ln_kernel<<<L_TOK / 8, 256>>>(t, ln2_w, ln2_b, hn);
    gemm_bf16_kernel<false><<<g320, 256, GEMM_SMEM_S>>>(
        hn, cwq2, nullptr, nullptr, nullptr, nullptr, 0,
        qh, nullptr, nullptr, scaleQ, L_TOK, nullptr,
        L_TOK, C_DIM, C_DIM, 0);
    attn_reg_kernel<<<attnGrid, 256, ATTN_SMEM>>>(qh, k2h, v2h, a, LCTX, LCTXP);
    gemm_bf16_kernel<false><<<g320, 256, GEMM_SMEM_S>>>(
        a, cwo2, bo2, t, t, nullptr, 0,
        nullptr, nullptr, nullptr, 0.f, 0, nullptr,
        L_TOK, C_DIM, C_DIM, 0);

    // ---- feed-forward ----
    ln_kernel<<<L_TOK / 8, 256>>>(t, ln3_w, ln3_b, hn);
    gemm_bf16_kernel<true><<<gFF1, 256, GEMM_SMEM_D>>>(
        hn, cwff1, bff1, nullptr, nullptr, nullptr, 0,
        nullptr, nullptr, nullptr, 0.f, 0, gg,
        L_TOK, 2 * FFI, C_DIM, 0);
    gemm_bf16_kernel<false><<<g320, 256, GEMM_SMEM_S>>>(
        gg, cwff2, bff2, t, t, tb, C_DIM,
        nullptr, nullptr, nullptr, 0.f, 0, nullptr,
        L_TOK, C_DIM, FFI, 0);

    // ---- proj_out (+ x residual), channel-major store ----
    gemm_bf16_kernel<false><<<g320, 256, GEMM_SMEM_S>>>(
        tb, cwout, b_out, x, out, nullptr, 0,
        nullptr, nullptr, nullptr, 0.f, 0, nullptr,
        L_TOK, C_DIM, C_DIM, 1);
}